// round 8
// baseline (speedup 1.0000x reference)
#include <cuda_runtime.h>

// ---------------------------------------------------------------------------
// VQ-VAE forward, fp32, Eigen-chain-order-exact encoder/VQ, f32x2-packed FMA.
// Round 7: round-5 base (passing); e2/e3/d1 remapped to 4 ow x 16 oc per
// thread (256 thr, no reg caps, per-kh weight staging). Others verbatim R5.
// ---------------------------------------------------------------------------

typedef unsigned long long u64;

__device__ float g_h1[64 * 32 * 128 * 128];
__device__ float g_h2[64 * 64 * 64 * 64];
__device__ float g_d1o[64 * 32 * 64 * 64];
__device__ float g_d2o[64 * 64 * 128 * 128];
__device__ float g_en[512];
__device__ float g_embT[64 * 512];   // [c][code]

__device__ __forceinline__ u64 pk2(float x, float y) {
    u64 r; asm("mov.b64 %0, {%1, %2};" : "=l"(r) : "f"(x), "f"(y)); return r;
}
__device__ __forceinline__ u64 f2fma(u64 a, u64 b, u64 c) {
    u64 d; asm("fma.rn.f32x2 %0, %1, %2, %3;" : "=l"(d) : "l"(a), "l"(b), "l"(c)); return d;
}
__device__ __forceinline__ float2 upk(u64 v) {
    float2 f; asm("mov.b64 {%0, %1}, %2;" : "=f"(f.x), "=f"(f.y) : "l"(v)); return f;
}

// --------------- codebook norms + transpose (verbatim R5) ------------------
__global__ void k_en(const float* __restrict__ emb) {
    int k = blockIdx.x * blockDim.x + threadIdx.x;
    if (k < 512) {
        float s = 0.f;
        for (int c = 0; c < 64; c++) {
            float v = emb[k * 64 + c];
            s = __fadd_rn(s, __fmul_rn(v, v));
            g_embT[c * 512 + k] = v;
        }
        g_en[k] = s;
    }
}

// ------------------------- e1 (verbatim R5) --------------------------------
__global__ __launch_bounds__(128) void k_e1(const float* __restrict__ x,
                                            const float* __restrict__ w,
                                            const float* __restrict__ b) {
    __shared__ float s_in[4 * 258];
    __shared__ float s_w[512];
    const int oh = blockIdx.x, n = blockIdx.y, t = threadIdx.x;
    const int lane = t & 31, wrp = t >> 5;
    {
        int r = wrp;
        int ih = 2 * oh - 1 + r;
        bool rowok = (ih >= 0 && ih < 256);
        const float* src = x + n * 65536 + ih * 256;
        float* dst = s_in + r * 258;
#pragma unroll
        for (int k = 0; k < 9; k++) {
            int c = lane + 32 * k;
            if (c < 258) {
                int iw = c - 1;
                dst[c] = (rowok && iw >= 0 && iw < 256) ? src[iw] : 0.f;
            }
        }
    }
    for (int i = t; i < 512; i += 128) s_w[i] = w[i];
    __syncthreads();
    float acc[32];
#pragma unroll
    for (int o = 0; o < 32; o++) acc[o] = 0.f;
    const int ow = t;
#pragma unroll
    for (int k = 0; k < 16; k++) {
        float v = s_in[(k >> 2) * 258 + 2 * ow + (k & 3)];
#pragma unroll
        for (int o = 0; o < 32; o++) acc[o] = fmaf(v, s_w[o * 16 + k], acc[o]);
    }
    for (int o = 0; o < 32; o++) {
        float r = __fadd_rn(acc[o], b[o]);
        g_h1[((n * 32 + o) * 128 + oh) * 128 + ow] = r > 0.f ? r : 0.f;
    }
}

// ------------------------- e2: 32->64, k4 s2 p1, relu ----------------------
// Block: 4 oh x 64 ow x 64 oc, 256 thr. Thread: 4 ow (tow+16i) x 16 oc.
// Chain: kh, kw outer; ic 0..31 innermost (Eigen) — unchanged.
__global__ __launch_bounds__(256) void k_e2(const float* __restrict__ w,
                                            const float* __restrict__ b) {
    extern __shared__ float sm[];
    float* s_in = sm;            // [rr(10)][ic(32)][130] = 41600
    float* s_w  = sm + 41600;    // per kh: [kw(4)][ic(32)][oc(64)] = 8192
    const int oh0 = blockIdx.x * 4, n = blockIdx.y, t = threadIdx.x;
    const int tow = t & 15, tog = (t >> 4) & 3, toh = t >> 6;   // toh 0..3
    const int lane = t & 31, wrp = t >> 5;
#pragma unroll 1
    for (int m = 0; m < 40; m++) {           // 320 rows = [rr10][ic32]
        int row = wrp * 40 + m;
        int rr = row >> 5, ic = row & 31;
        int ih = 2 * oh0 - 1 + rr;
        bool rowok = (ih >= 0 && ih < 128);
        const float* src = g_h1 + ((n * 32 + ic) * 128 + ih) * 128;
        float* dst = s_in + row * 130;
#pragma unroll
        for (int k = 0; k < 5; k++) {
            int c = lane + 32 * k;
            if (c < 130) {
                int iw = c - 1;
                dst[c] = (rowok && iw >= 0 && iw < 128) ? src[iw] : 0.f;
            }
        }
    }
    u64 acc[4][8];
#pragma unroll
    for (int i = 0; i < 4; i++)
#pragma unroll
        for (int j = 0; j < 8; j++) acc[i][j] = 0ull;
#pragma unroll 1
    for (int kh = 0; kh < 4; kh++) {
        __syncthreads();
        for (int i = t; i < 8192; i += 256) {
            int kw = i >> 11, ic = (i >> 6) & 31, oc = i & 63;
            s_w[i] = w[((oc * 32 + ic) << 4) + (kh << 2) + kw];
        }
        __syncthreads();
#pragma unroll
        for (int kw = 0; kw < 4; kw++) {
            const float* pin = s_in + (2 * toh + kh) * 4160 + 2 * tow + kw;
            const float* pwb = s_w + (kw << 11) + (tog << 4);
#pragma unroll 2
            for (int ic = 0; ic < 32; ic++) {
                const float* pw = pwb + (ic << 6);
                ulonglong2 w0 = *(const ulonglong2*)(pw);
                ulonglong2 w1 = *(const ulonglong2*)(pw + 4);
                ulonglong2 w2 = *(const ulonglong2*)(pw + 8);
                ulonglong2 w3 = *(const ulonglong2*)(pw + 12);
                const float* q = pin + ic * 130;
#pragma unroll
                for (int i = 0; i < 4; i++) {
                    float v = q[32 * i];
                    u64 vv = pk2(v, v);
                    acc[i][0] = f2fma(vv, w0.x, acc[i][0]);
                    acc[i][1] = f2fma(vv, w0.y, acc[i][1]);
                    acc[i][2] = f2fma(vv, w1.x, acc[i][2]);
                    acc[i][3] = f2fma(vv, w1.y, acc[i][3]);
                    acc[i][4] = f2fma(vv, w2.x, acc[i][4]);
                    acc[i][5] = f2fma(vv, w2.y, acc[i][5]);
                    acc[i][6] = f2fma(vv, w3.x, acc[i][6]);
                    acc[i][7] = f2fma(vv, w3.y, acc[i][7]);
                }
            }
        }
    }
    const int oh = oh0 + toh;
#pragma unroll
    for (int i = 0; i < 4; i++) {
        int ow = tow + 16 * i;
#pragma unroll
        for (int j = 0; j < 8; j++) {
            float2 f = upk(acc[i][j]);
            int oc0 = tog * 16 + 2 * j;
            float r0 = __fadd_rn(f.x, b[oc0]);
            float r1 = __fadd_rn(f.y, b[oc0 + 1]);
            g_h2[((n * 64 + oc0) * 64 + oh) * 64 + ow]     = r0 > 0.f ? r0 : 0.f;
            g_h2[((n * 64 + oc0 + 1) * 64 + oh) * 64 + ow] = r1 > 0.f ? r1 : 0.f;
        }
    }
}

// ------------------------- e3: 64->64, k3 s1 p1, relu ----------------------
// Block: 4 oh x 64 ow x 64 oc, 256 thr. Thread: 4 ow x 16 oc.
__global__ __launch_bounds__(256) void k_e3(const float* __restrict__ w,
                                            const float* __restrict__ b,
                                            float* __restrict__ ze) {
    extern __shared__ float sm[];
    float* s_in = sm;            // [r(6)][ic(64)][66] = 25344
    float* s_w  = sm + 25344;    // per kh: [kw(3)][ic(64)][oc(64)] = 12288
    const int oh0 = blockIdx.x * 4, n = blockIdx.y, t = threadIdx.x;
    const int tow = t & 15, tog = (t >> 4) & 3, toh = t >> 6;
    const int lane = t & 31, wrp = t >> 5;
#pragma unroll 1
    for (int m = 0; m < 48; m++) {           // 384 rows = [r6][ic64]
        int row = wrp * 48 + m;
        int r = row >> 6, ic = row & 63;
        int ih = oh0 - 1 + r;
        bool rowok = (ih >= 0 && ih < 64);
        const float* src = g_h2 + ((n * 64 + ic) * 64 + ih) * 64;
        float* dst = s_in + row * 66;
#pragma unroll
        for (int k = 0; k < 3; k++) {
            int c = lane + 32 * k;
            if (c < 66) {
                int iw = c - 1;
                dst[c] = (rowok && iw >= 0 && iw < 64) ? src[iw] : 0.f;
            }
        }
    }
    u64 acc[4][8];
#pragma unroll
    for (int i = 0; i < 4; i++)
#pragma unroll
        for (int j = 0; j < 8; j++) acc[i][j] = 0ull;
#pragma unroll 1
    for (int kh = 0; kh < 3; kh++) {
        __syncthreads();
        for (int i = t; i < 12288; i += 256) {
            int kw = i >> 12, ic = (i >> 6) & 63, oc = i & 63;
            s_w[i] = w[(oc * 64 + ic) * 9 + kh * 3 + kw];
        }
        __syncthreads();
#pragma unroll
        for (int kw = 0; kw < 3; kw++) {
            const float* pin = s_in + (toh + kh) * 4224 + tow + kw;
            const float* pwb = s_w + (kw << 12) + (tog << 4);
#pragma unroll 2
            for (int ic = 0; ic < 64; ic++) {
                const float* pw = pwb + (ic << 6);
                ulonglong2 w0 = *(const ulonglong2*)(pw);
                ulonglong2 w1 = *(const ulonglong2*)(pw + 4);
                ulonglong2 w2 = *(const ulonglong2*)(pw + 8);
                ulonglong2 w3 = *(const ulonglong2*)(pw + 12);
                const float* q = pin + ic * 66;
#pragma unroll
                for (int i = 0; i < 4; i++) {
                    float v = q[16 * i];
                    u64 vv = pk2(v, v);
                    acc[i][0] = f2fma(vv, w0.x, acc[i][0]);
                    acc[i][1] = f2fma(vv, w0.y, acc[i][1]);
                    acc[i][2] = f2fma(vv, w1.x, acc[i][2]);
                    acc[i][3] = f2fma(vv, w1.y, acc[i][3]);
                    acc[i][4] = f2fma(vv, w2.x, acc[i][4]);
                    acc[i][5] = f2fma(vv, w2.y, acc[i][5]);
                    acc[i][6] = f2fma(vv, w3.x, acc[i][6]);
                    acc[i][7] = f2fma(vv, w3.y, acc[i][7]);
                }
            }
        }
    }
    const int oh = oh0 + toh;
#pragma unroll
    for (int i = 0; i < 4; i++) {
        int ow = tow + 16 * i;
#pragma unroll
        for (int j = 0; j < 8; j++) {
            float2 f = upk(acc[i][j]);
            int oc0 = tog * 16 + 2 * j;
            float r0 = __fadd_rn(f.x, b[oc0]);
            float r1 = __fadd_rn(f.y, b[oc0 + 1]);
            ze[((n * 64 + oc0) * 64 + oh) * 64 + ow]     = r0 > 0.f ? r0 : 0.f;
            ze[((n * 64 + oc0 + 1) * 64 + oh) * 64 + ow] = r1 > 0.f ? r1 : 0.f;
        }
    }
}

// ------------------------- VQ (verbatim R5) --------------------------------
__global__ __launch_bounds__(256) void k_vq(const float* __restrict__ ze,
                                            const float* __restrict__ emb,
                                            float* __restrict__ zq) {
    __shared__ __align__(16) float s_z[4096];   // [c(64)][pos(64)]
    __shared__ __align__(16) float s_e[4096];   // [c(64)][code_local(64)]
    __shared__ float s_zz[64];
    __shared__ float s_en[512];
    __shared__ float s_bv[256];
    __shared__ int s_bi[256];
    __shared__ int s_idx[64];
    const int h = blockIdx.x, n = blockIdx.y, t = threadIdx.x;
    const int pos = t & 63, kg = t >> 6;
    for (int i = t; i < 4096; i += 256)
        s_z[i] = ze[(n * 64 + (i >> 6)) * 4096 + h * 64 + (i & 63)];
    for (int i = t; i < 512; i += 256) s_en[i] = g_en[i];
    __syncthreads();
    if (t < 64) {
        float a = 0.f;
        for (int c = 0; c < 64; c++) {
            float v = s_z[c * 64 + t];
            a = __fadd_rn(a, __fmul_rn(v, v));
        }
        s_zz[t] = a;
    }
    float bv = 3.4e38f;
    int bi = 0;
    for (int ch = 0; ch < 8; ch++) {
        __syncthreads();
        for (int i = t; i < 4096; i += 256)
            s_e[i] = g_embT[(i >> 6) * 512 + ch * 64 + (i & 63)];
        __syncthreads();
        const float zz = s_zz[pos];
        u64 dot[8];
#pragma unroll
        for (int j = 0; j < 8; j++) dot[j] = 0ull;
#pragma unroll 4
        for (int c = 0; c < 64; c++) {
            float v = s_z[c * 64 + pos];
            u64 vv = pk2(v, v);
            const ulonglong2* pe = (const ulonglong2*)(s_e + c * 64 + kg * 16);
#pragma unroll
            for (int j = 0; j < 4; j++) {
                ulonglong2 e2v = pe[j];
                dot[2 * j]     = f2fma(vv, e2v.x, dot[2 * j]);
                dot[2 * j + 1] = f2fma(vv, e2v.y, dot[2 * j + 1]);
            }
        }
#pragma unroll
        for (int j = 0; j < 8; j++) {
            float2 f = upk(dot[j]);
            int code0 = ch * 64 + kg * 16 + 2 * j;
            float d0 = __fadd_rn(__fsub_rn(zz, __fmul_rn(2.0f, f.x)), s_en[code0]);
            float d1 = __fadd_rn(__fsub_rn(zz, __fmul_rn(2.0f, f.y)), s_en[code0 + 1]);
            if (d0 < bv) { bv = d0; bi = code0; }
            if (d1 < bv) { bv = d1; bi = code0 + 1; }
        }
    }
    s_bv[t] = bv;
    s_bi[t] = bi;
    __syncthreads();
    if (t < 64) {
        for (int q = 1; q < 4; q++) {
            float v2 = s_bv[t + q * 64];
            int i2 = s_bi[t + q * 64];
            if (v2 < bv || (v2 == bv && i2 < bi)) { bv = v2; bi = i2; }
        }
        s_idx[t] = bi;
    }
    __syncthreads();
    for (int i = t; i < 4096; i += 256) {
        int c = i >> 6, wq = i & 63;
        zq[(n * 64 + c) * 4096 + h * 64 + wq] = emb[s_idx[wq] * 64 + c];
    }
}

// --------------- d1: convT 64->32, k3 s1 p1, relu; in = ze+(zq-ze) ---------
// Block: 8 oh x 64 ow x 32 oc, 256 thr. Thread: 4 ow x 16 oc.
__global__ __launch_bounds__(256) void k_d1(const float* __restrict__ ze,
                                            const float* __restrict__ zq,
                                            const float* __restrict__ w,
                                            const float* __restrict__ b) {
    extern __shared__ float sm[];
    float* s_in = sm;            // [r(10)][ic(64)][66] = 42240
    float* s_w  = sm + 42240;    // per kh: [kw(3)][ic(64)][oc(32)] = 6144
    const int oh0 = blockIdx.x * 8, n = blockIdx.y, t = threadIdx.x;
    const int tow = t & 15, tog = (t >> 4) & 1, toh = t >> 5;   // toh 0..7
    const int lane = t & 31, wrp = t >> 5;
#pragma unroll 1
    for (int m = 0; m < 80; m++) {           // 640 rows = [r10][ic64]
        int row = wrp * 80 + m;
        int r = row >> 6, ic = row & 63;
        int ih = oh0 - 1 + r;
        bool rowok = (ih >= 0 && ih < 64);
        const float* pz = ze + ((n * 64 + ic) * 64 + ih) * 64;
        const float* pq = zq + ((n * 64 + ic) * 64 + ih) * 64;
        float* dst = s_in + row * 66;
#pragma unroll
        for (int k = 0; k < 3; k++) {
            int c = lane + 32 * k;
            if (c < 66) {
                int iw = c - 1;
                float v = 0.f;
                if (rowok && iw >= 0 && iw < 64) {
                    float a = pz[iw], q = pq[iw];
                    v = __fadd_rn(a, __fsub_rn(q, a));
                }
                dst[c] = v;
            }
        }
    }
    u64 acc[4][8];
#pragma unroll
    for (int i = 0; i < 4; i++)
#pragma unroll
        for (int j = 0; j < 8; j++) acc[i][j] = 0ull;
#pragma unroll 1
    for (int kh = 0; kh < 3; kh++) {
        __syncthreads();
        for (int i = t; i < 6144; i += 256) {
            int kw = i >> 11, ic = (i >> 5) & 63, oc = i & 31;
            s_w[i] = w[(ic * 32 + oc) * 9 + 8 - kh * 3 - kw];
        }
        __syncthreads();
#pragma unroll
        for (int kw = 0; kw < 3; kw++) {
            const float* pin = s_in + (toh + kh) * 4224 + tow + kw;
            const float* pwb = s_w + (kw << 11) + (tog << 4);
#pragma unroll 2
            for (int ic = 0; ic < 64; ic++) {
                const float* pw = pwb + (ic << 5);
                ulonglong2 w0 = *(const ulonglong2*)(pw);
                ulonglong2 w1 = *(const ulonglong2*)(pw + 4);
                ulonglong2 w2 = *(const ulonglong2*)(pw + 8);
                ulonglong2 w3 = *(const ulonglong2*)(pw + 12);
                const float* q = pin + ic * 66;
#pragma unroll
                for (int i = 0; i < 4; i++) {
                    float v = q[16 * i];
                    u64 vv = pk2(v, v);
                    acc[i][0] = f2fma(vv, w0.x, acc[i][0]);
                    acc[i][1] = f2fma(vv, w0.y, acc[i][1]);
                    acc[i][2] = f2fma(vv, w1.x, acc[i][2]);
                    acc[i][3] = f2fma(vv, w1.y, acc[i][3]);
                    acc[i][4] = f2fma(vv, w2.x, acc[i][4]);
                    acc[i][5] = f2fma(vv, w2.y, acc[i][5]);
                    acc[i][6] = f2fma(vv, w3.x, acc[i][6]);
                    acc[i][7] = f2fma(vv, w3.y, acc[i][7]);
                }
            }
        }
    }
    const int oh = oh0 + toh;
#pragma unroll
    for (int i = 0; i < 4; i++) {
        int ow = tow + 16 * i;
#pragma unroll
        for (int j = 0; j < 8; j++) {
            float2 f = upk(acc[i][j]);
            int oc0 = tog * 16 + 2 * j;
            float r0 = f.x + b[oc0];
            float r1 = f.y + b[oc0 + 1];
            g_d1o[((n * 32 + oc0) * 64 + oh) * 64 + ow]     = r0 > 0.f ? r0 : 0.f;
            g_d1o[((n * 32 + oc0 + 1) * 64 + oh) * 64 + ow] = r1 > 0.f ? r1 : 0.f;
        }
    }
}

// --------------- d2 (verbatim R5) ------------------------------------------
__global__ __launch_bounds__(256) void k_d2(const float* __restrict__ w,
                                            const float* __restrict__ b) {
    __shared__ __align__(16) float s_in[2112];   // [r(2)][ic(16)][66]
    __shared__ __align__(16) float s_w[8192];    // [ic(16)][r(2)][kw(4)][oc(64)]
    const int oh = blockIdx.x, n = blockIdx.y, t = threadIdx.x;
    const int p = t & 1, u = (t >> 1) & 15, tog = t >> 5;
    const int lane = t & 31, wrp = t >> 5;
    const int kh_a = 1 - (oh & 1);
    const int ih_a = (oh + 1 - kh_a) >> 1;
    const int kw_a = 1 - p;
    u64 acc[4][4];
#pragma unroll
    for (int i = 0; i < 4; i++)
#pragma unroll
        for (int j = 0; j < 4; j++) acc[i][j] = 0ull;
#pragma unroll 1
    for (int cc = 0; cc < 2; cc++) {
        __syncthreads();
#pragma unroll
        for (int m = 0; m < 4; m++) {
            int row = wrp * 4 + m;
            int r = row >> 4, ic = row & 15;
            int ih = (r == 0) ? ih_a : ih_a - 1;
            bool rowok = (ih >= 0 && ih < 64);
            const float* src = g_d1o + ((n * 32 + cc * 16 + ic) * 64 + ih) * 64;
            float* dst = s_in + row * 66;
#pragma unroll
            for (int k = 0; k < 3; k++) {
                int c = lane + 32 * k;
                if (c < 66) {
                    int iw = c - 1;
                    dst[c] = (rowok && iw >= 0 && iw < 64) ? src[iw] : 0.f;
                }
            }
        }
        for (int i = t; i < 8192; i += 256) {
            int ic = i >> 9, rem = i & 511;
            int r = rem >> 8, kw = (rem >> 6) & 3, oc = rem & 63;
            s_w[i] = w[(((cc * 16 + ic) * 64 + oc) << 4) + (kh_a + 2 * r) * 4 + kw];
        }
        __syncthreads();
#pragma unroll 2
        for (int ic = 0; ic < 16; ic++) {
#pragma unroll
            for (int r = 0; r < 2; r++) {
#pragma unroll
                for (int m = 0; m < 2; m++) {
                    int kw = kw_a + 2 * m;
                    const ulonglong2* pw = (const ulonglong2*)(s_w + ((ic * 2 + r) * 4 + kw) * 64 + tog * 8);
                    const float* q = s_in + r * 1056 + ic * 66 + u + p - m + 1;
                    ulonglong2 w01 = pw[0], w23 = pw[1];
#pragma unroll
                    for (int i = 0; i < 4; i++) {
                        float v = q[16 * i];
                        u64 vv = pk2(v, v);
                        acc[i][0] = f2fma(vv, w01.x, acc[i][0]);
                        acc[i][1] = f2fma(vv, w01.y, acc[i][1]);
                        acc[i][2] = f2fma(vv, w23.x, acc[i][2]);
                        acc[i][3] = f2fma(vv, w23.y, acc[i][3]);
                    }
                }
            }
        }
    }
#pragma unroll
    for (int i = 0; i < 4; i++) {
        int ow = 2 * (u + 16 * i) + p;
#pragma unroll
        for (int j = 0; j < 4; j++) {
            float2 f = upk(acc[i][j]);
            int oc0 = tog * 8 + 2 * j;
            float r0 = f.x + b[oc0];
            float r1 = f.y + b[oc0 + 1];
            g_d2o[((n * 64 + oc0) * 128 + oh) * 128 + ow]     = r0 > 0.f ? r0 : 0.f;
            g_d2o[((n * 64 + oc0 + 1) * 128 + oh) * 128 + ow] = r1 > 0.f ? r1 : 0.f;
        }
    }
}

// --------------- d3 (verbatim R5) ------------------------------------------
__global__ __launch_bounds__(256) void k_d3(const float* __restrict__ w,
                                            const float* __restrict__ bb,
                                            float* __restrict__ xh) {
    __shared__ float s_in[8320];   // [r(2)][ic(32)][130]
    __shared__ float s_w[512];
    const int oh = blockIdx.x, n = blockIdx.y, t = threadIdx.x;
    const int ow = t;
    const int lane = t & 31, wrp = t >> 5;
    const int kh_a = 1 - (oh & 1);
    const int ih_a = (oh + 1 - kh_a) >> 1;
    const int ih_b = ih_a - 1;
    const int kw_a = 1 - (ow & 1);
    const int iw_a = (ow + 1 - kw_a) >> 1;
    for (int i = t; i < 512; i += 256) {
        int ic = i >> 3, r = (i >> 2) & 1, kw = i & 3;
        int kh = kh_a + 2 * r;
        s_w[i] = w[ic * 16 + kh * 4 + kw];
    }
    float acc = 0.f;
#pragma unroll 1
    for (int cc = 0; cc < 2; cc++) {
        __syncthreads();
#pragma unroll
        for (int m = 0; m < 8; m++) {
            int row = wrp * 8 + m;
            int r = row >> 5, ic = row & 31;
            int ih = (r == 0) ? ih_a : ih_b;
            bool rowok = (ih >= 0 && ih < 128);
            const float* src = g_d2o + ((n * 64 + cc * 32 + ic) * 128 + ih) * 128;
            float* dst = s_in + row * 130;
#pragma unroll
            for (int k = 0; k < 5; k++) {
                int c = lane + 32 * k;
                if (c < 130) {
                    int iw = c - 1;
                    dst[c] = (rowok && iw >= 0 && iw < 128) ? src[iw] : 0.f;
                }
            }
        }
        __syncthreads();
#pragma unroll 4
        for (int ic = 0; ic < 32; ic++) {
#pragma unroll
            for (int r = 0; r < 2; r++) {
#pragma unroll
                for (int m = 0; m < 2; m++) {
                    float v = s_in[r * 4160 + ic * 130 + iw_a - m + 1];
                    acc = fmaf(v, s_w[((cc * 32 + ic) << 3) + r * 4 + kw_a + 2 * m], acc);
                }
            }
        }
    }
    xh[n * 65536 + oh * 256 + ow] = __fadd_rn(acc, bb[0]);
}

// ---------------------------------------------------------------------------
extern "C" void kernel_launch(void* const* d_in, const int* in_sizes, int n_in,
                              void* d_out, int out_size) {
    const float* x   = (const float*)d_in[0];
    const float* e1w = (const float*)d_in[1];
    const float* e1b = (const float*)d_in[2];
    const float* e2w = (const float*)d_in[3];
    const float* e2b = (const float*)d_in[4];
    const float* e3w = (const float*)d_in[5];
    const float* e3b = (const float*)d_in[6];
    const float* emb = (const float*)d_in[7];
    const float* d1w = (const float*)d_in[8];
    const float* d1b = (const float*)d_in[9];
    const float* d2w = (const float*)d_in[10];
    const float* d2b = (const float*)d_in[11];
    const float* d3w = (const float*)d_in[12];
    const float* d3b = (const float*)d_in[13];

    float* out = (float*)d_out;
    float* xh = out;
    float* ze = out + 4194304;
    float* zq = out + 4194304 + 16777216;

    static bool attr_done = false;
    if (!attr_done) {
        cudaFuncSetAttribute(k_e2, cudaFuncAttributeMaxDynamicSharedMemorySize, 199168);
        cudaFuncSetAttribute(k_e3, cudaFuncAttributeMaxDynamicSharedMemorySize, 150528);
        cudaFuncSetAttribute(k_d1, cudaFuncAttributeMaxDynamicSharedMemorySize, 193536);
        attr_done = true;
    }

    k_en<<<2, 256>>>(emb);
    k_e1<<<dim3(128, 64), 128>>>(x, e1w, e1b);
    k_e2<<<dim3(16, 64), 256, 199168>>>(e2w, e2b);
    k_e3<<<dim3(16, 64), 256, 150528>>>(e3w, e3b, ze);
    k_vq<<<dim3(64, 64), 256>>>(ze, emb, zq);
    k_d1<<<dim3(8, 64), 256, 193536>>>(ze, zq, d1w, d1b);
    k_d2<<<dim3(128, 64), 256>>>(d2w, d2b);
    k_d3<<<dim3(256, 64), 256>>>(d3w, d3b, xh);
}

// round 9
// speedup vs baseline: 1.0119x; 1.0119x over previous
#include <cuda_runtime.h>

// ---------------------------------------------------------------------------
// VQ-VAE forward, fp32, Eigen-chain-order-exact encoder/VQ, f32x2-packed FMA.
// Round 8: 2 ow x 16 oc threads, 2 CTAs/SM (smem <= 110KB), conflict-free
// LDS (parity-split s_in for the stride-2 e2). No launch_bounds reg caps.
// ---------------------------------------------------------------------------

typedef unsigned long long u64;

__device__ float g_h1[64 * 32 * 128 * 128];
__device__ float g_h2[64 * 64 * 64 * 64];
__device__ float g_d1o[64 * 32 * 64 * 64];
__device__ float g_d2o[64 * 64 * 128 * 128];
__device__ float g_en[512];
__device__ float g_embT[64 * 512];   // [c][code]

__device__ __forceinline__ u64 pk2(float x, float y) {
    u64 r; asm("mov.b64 %0, {%1, %2};" : "=l"(r) : "f"(x), "f"(y)); return r;
}
__device__ __forceinline__ u64 f2fma(u64 a, u64 b, u64 c) {
    u64 d; asm("fma.rn.f32x2 %0, %1, %2, %3;" : "=l"(d) : "l"(a), "l"(b), "l"(c)); return d;
}
__device__ __forceinline__ float2 upk(u64 v) {
    float2 f; asm("mov.b64 {%0, %1}, %2;" : "=f"(f.x), "=f"(f.y) : "l"(v)); return f;
}

// --------------- codebook norms + transpose --------------------------------
__global__ void k_en(const float* __restrict__ emb) {
    int k = blockIdx.x * blockDim.x + threadIdx.x;
    if (k < 512) {
        float s = 0.f;
        for (int c = 0; c < 64; c++) {
            float v = emb[k * 64 + c];
            s = __fadd_rn(s, __fmul_rn(v, v));
            g_embT[c * 512 + k] = v;
        }
        g_en[k] = s;
    }
}

// ------------------------- e1 (verbatim) -----------------------------------
__global__ __launch_bounds__(128) void k_e1(const float* __restrict__ x,
                                            const float* __restrict__ w,
                                            const float* __restrict__ b) {
    __shared__ float s_in[4 * 258];
    __shared__ float s_w[512];
    const int oh = blockIdx.x, n = blockIdx.y, t = threadIdx.x;
    const int lane = t & 31, wrp = t >> 5;
    {
        int r = wrp;
        int ih = 2 * oh - 1 + r;
        bool rowok = (ih >= 0 && ih < 256);
        const float* src = x + n * 65536 + ih * 256;
        float* dst = s_in + r * 258;
#pragma unroll
        for (int k = 0; k < 9; k++) {
            int c = lane + 32 * k;
            if (c < 258) {
                int iw = c - 1;
                dst[c] = (rowok && iw >= 0 && iw < 256) ? src[iw] : 0.f;
            }
        }
    }
    for (int i = t; i < 512; i += 128) s_w[i] = w[i];
    __syncthreads();
    float acc[32];
#pragma unroll
    for (int o = 0; o < 32; o++) acc[o] = 0.f;
    const int ow = t;
#pragma unroll
    for (int k = 0; k < 16; k++) {
        float v = s_in[(k >> 2) * 258 + 2 * ow + (k & 3)];
#pragma unroll
        for (int o = 0; o < 32; o++) acc[o] = fmaf(v, s_w[o * 16 + k], acc[o]);
    }
    for (int o = 0; o < 32; o++) {
        float r = __fadd_rn(acc[o], b[o]);
        g_h1[((n * 32 + o) * 128 + oh) * 128 + ow] = r > 0.f ? r : 0.f;
    }
}

// ------------------------- e2: 32->64, k4 s2 p1, relu ----------------------
// Block: 2 oh x 64 ow x 64 oc, 256 thr. Thread: 2 ow (tow+32i) x 16 oc.
// s_in parity-split: [rr(6)][ic(32)][par(2)][66]; col c=2ow+kw -> par=kw&1,
// cp=ow+(kw>>1) -> stride-1 over lanes. Chain: kh,kw outer; ic innermost.
__global__ __launch_bounds__(256) void k_e2(const float* __restrict__ w,
                                            const float* __restrict__ b) {
    extern __shared__ float sm[];
    float* s_in = sm;            // 6*32*132 = 25344
    float* s_w  = sm + 25344;    // per (kh,kw): [ic(32)][oc(64)] = 2048
    const int oh0 = blockIdx.x * 2, n = blockIdx.y, t = threadIdx.x;
    const int tow = t & 31, tog = (t >> 5) & 3, toh = t >> 7;
    const int lane = t & 31, wrp = t >> 5;
#pragma unroll 1
    for (int m = 0; m < 24; m++) {           // 192 rows = [rr6][ic32]
        int row = wrp * 24 + m;
        int rr = row >> 5, ic = row & 31;
        int ih = 2 * oh0 - 1 + rr;
        bool rowok = (ih >= 0 && ih < 128);
        const float* src = g_h1 + ((n * 32 + ic) * 128 + ih) * 128;
        float* dst = s_in + row * 132;
#pragma unroll
        for (int k = 0; k < 5; k++) {
            int c = lane + 32 * k;
            if (c < 130) {
                int iw = c - 1;
                dst[(c & 1) * 66 + (c >> 1)] =
                    (rowok && iw >= 0 && iw < 128) ? src[iw] : 0.f;
            }
        }
    }
    u64 acc[2][8];
#pragma unroll
    for (int i = 0; i < 2; i++)
#pragma unroll
        for (int j = 0; j < 8; j++) acc[i][j] = 0ull;
#pragma unroll 1
    for (int kh = 0; kh < 4; kh++) {
#pragma unroll 1
        for (int kw = 0; kw < 4; kw++) {
            __syncthreads();
            for (int i = t; i < 2048; i += 256) {
                int ic = i >> 6, oc = i & 63;
                s_w[i] = w[((oc * 32 + ic) << 4) + (kh << 2) + kw];
            }
            __syncthreads();
            const float* pin = s_in + (2 * toh + kh) * 32 * 132
                                    + (kw & 1) * 66 + (kw >> 1) + tow;
            const float* pwb = s_w + (tog << 4);
#pragma unroll 4
            for (int ic = 0; ic < 32; ic++) {
                const float* pw = pwb + (ic << 6);
                ulonglong2 w0 = *(const ulonglong2*)(pw);
                ulonglong2 w1 = *(const ulonglong2*)(pw + 4);
                ulonglong2 w2 = *(const ulonglong2*)(pw + 8);
                ulonglong2 w3 = *(const ulonglong2*)(pw + 12);
                const float* q = pin + ic * 132;
#pragma unroll
                for (int i = 0; i < 2; i++) {
                    float v = q[32 * i];
                    u64 vv = pk2(v, v);
                    acc[i][0] = f2fma(vv, w0.x, acc[i][0]);
                    acc[i][1] = f2fma(vv, w0.y, acc[i][1]);
                    acc[i][2] = f2fma(vv, w1.x, acc[i][2]);
                    acc[i][3] = f2fma(vv, w1.y, acc[i][3]);
                    acc[i][4] = f2fma(vv, w2.x, acc[i][4]);
                    acc[i][5] = f2fma(vv, w2.y, acc[i][5]);
                    acc[i][6] = f2fma(vv, w3.x, acc[i][6]);
                    acc[i][7] = f2fma(vv, w3.y, acc[i][7]);
                }
            }
        }
    }
    const int oh = oh0 + toh;
#pragma unroll
    for (int i = 0; i < 2; i++) {
        int ow = tow + 32 * i;
#pragma unroll
        for (int j = 0; j < 8; j++) {
            float2 f = upk(acc[i][j]);
            int oc0 = tog * 16 + 2 * j;
            float r0 = __fadd_rn(f.x, b[oc0]);
            float r1 = __fadd_rn(f.y, b[oc0 + 1]);
            g_h2[((n * 64 + oc0) * 64 + oh) * 64 + ow]     = r0 > 0.f ? r0 : 0.f;
            g_h2[((n * 64 + oc0 + 1) * 64 + oh) * 64 + ow] = r1 > 0.f ? r1 : 0.f;
        }
    }
}

// ------------------------- e3: 64->64, k3 s1 p1, relu ----------------------
// Block: 2 oh x 64 ow x 64 oc, 256 thr. Thread: 2 ow (tow+32i) x 16 oc.
__global__ __launch_bounds__(256) void k_e3(const float* __restrict__ w,
                                            const float* __restrict__ b,
                                            float* __restrict__ ze) {
    extern __shared__ float sm[];
    float* s_in = sm;            // [r(4)][ic(64)][66] = 16896
    float* s_w  = sm + 16896;    // per (kh,kw): [ic(64)][oc(64)] = 4096
    const int oh0 = blockIdx.x * 2, n = blockIdx.y, t = threadIdx.x;
    const int tow = t & 31, tog = (t >> 5) & 3, toh = t >> 7;
    const int lane = t & 31, wrp = t >> 5;
#pragma unroll 1
    for (int m = 0; m < 32; m++) {           // 256 rows = [r4][ic64]
        int row = wrp * 32 + m;
        int r = row >> 6, ic = row & 63;
        int ih = oh0 - 1 + r;
        bool rowok = (ih >= 0 && ih < 64);
        const float* src = g_h2 + ((n * 64 + ic) * 64 + ih) * 64;
        float* dst = s_in + row * 66;
#pragma unroll
        for (int k = 0; k < 3; k++) {
            int c = lane + 32 * k;
            if (c < 66) {
                int iw = c - 1;
                dst[c] = (rowok && iw >= 0 && iw < 64) ? src[iw] : 0.f;
            }
        }
    }
    u64 acc[2][8];
#pragma unroll
    for (int i = 0; i < 2; i++)
#pragma unroll
        for (int j = 0; j < 8; j++) acc[i][j] = 0ull;
#pragma unroll 1
    for (int kh = 0; kh < 3; kh++) {
#pragma unroll 1
        for (int kw = 0; kw < 3; kw++) {
            __syncthreads();
            for (int i = t; i < 4096; i += 256) {
                int ic = i >> 6, oc = i & 63;
                s_w[i] = w[(oc * 64 + ic) * 9 + kh * 3 + kw];
            }
            __syncthreads();
            const float* pin = s_in + (toh + kh) * 4224 + tow + kw;
            const float* pwb = s_w + (tog << 4);
#pragma unroll 4
            for (int ic = 0; ic < 64; ic++) {
                const float* pw = pwb + (ic << 6);
                ulonglong2 w0 = *(const ulonglong2*)(pw);
                ulonglong2 w1 = *(const ulonglong2*)(pw + 4);
                ulonglong2 w2 = *(const ulonglong2*)(pw + 8);
                ulonglong2 w3 = *(const ulonglong2*)(pw + 12);
                const float* q = pin + ic * 66;
#pragma unroll
                for (int i = 0; i < 2; i++) {
                    float v = q[32 * i];
                    u64 vv = pk2(v, v);
                    acc[i][0] = f2fma(vv, w0.x, acc[i][0]);
                    acc[i][1] = f2fma(vv, w0.y, acc[i][1]);
                    acc[i][2] = f2fma(vv, w1.x, acc[i][2]);
                    acc[i][3] = f2fma(vv, w1.y, acc[i][3]);
                    acc[i][4] = f2fma(vv, w2.x, acc[i][4]);
                    acc[i][5] = f2fma(vv, w2.y, acc[i][5]);
                    acc[i][6] = f2fma(vv, w3.x, acc[i][6]);
                    acc[i][7] = f2fma(vv, w3.y, acc[i][7]);
                }
            }
        }
    }
    const int oh = oh0 + toh;
#pragma unroll
    for (int i = 0; i < 2; i++) {
        int ow = tow + 32 * i;
#pragma unroll
        for (int j = 0; j < 8; j++) {
            float2 f = upk(acc[i][j]);
            int oc0 = tog * 16 + 2 * j;
            float r0 = __fadd_rn(f.x, b[oc0]);
            float r1 = __fadd_rn(f.y, b[oc0 + 1]);
            ze[((n * 64 + oc0) * 64 + oh) * 64 + ow]     = r0 > 0.f ? r0 : 0.f;
            ze[((n * 64 + oc0 + 1) * 64 + oh) * 64 + ow] = r1 > 0.f ? r1 : 0.f;
        }
    }
}

// ------------------------- VQ (verbatim R5) --------------------------------
__global__ __launch_bounds__(256) void k_vq(const float* __restrict__ ze,
                                            const float* __restrict__ emb,
                                            float* __restrict__ zq) {
    __shared__ __align__(16) float s_z[4096];   // [c(64)][pos(64)]
    __shared__ __align__(16) float s_e[4096];   // [c(64)][code_local(64)]
    __shared__ float s_zz[64];
    __shared__ float s_en[512];
    __shared__ float s_bv[256];
    __shared__ int s_bi[256];
    __shared__ int s_idx[64];
    const int h = blockIdx.x, n = blockIdx.y, t = threadIdx.x;
    const int pos = t & 63, kg = t >> 6;
    for (int i = t; i < 4096; i += 256)
        s_z[i] = ze[(n * 64 + (i >> 6)) * 4096 + h * 64 + (i & 63)];
    for (int i = t; i < 512; i += 256) s_en[i] = g_en[i];
    __syncthreads();
    if (t < 64) {
        float a = 0.f;
        for (int c = 0; c < 64; c++) {
            float v = s_z[c * 64 + t];
            a = __fadd_rn(a, __fmul_rn(v, v));
        }
        s_zz[t] = a;
    }
    float bv = 3.4e38f;
    int bi = 0;
    for (int ch = 0; ch < 8; ch++) {
        __syncthreads();
        for (int i = t; i < 4096; i += 256)
            s_e[i] = g_embT[(i >> 6) * 512 + ch * 64 + (i & 63)];
        __syncthreads();
        const float zz = s_zz[pos];
        u64 dot[8];
#pragma unroll
        for (int j = 0; j < 8; j++) dot[j] = 0ull;
#pragma unroll 4
        for (int c = 0; c < 64; c++) {
            float v = s_z[c * 64 + pos];
            u64 vv = pk2(v, v);
            const ulonglong2* pe = (const ulonglong2*)(s_e + c * 64 + kg * 16);
#pragma unroll
            for (int j = 0; j < 4; j++) {
                ulonglong2 e2v = pe[j];
                dot[2 * j]     = f2fma(vv, e2v.x, dot[2 * j]);
                dot[2 * j + 1] = f2fma(vv, e2v.y, dot[2 * j + 1]);
            }
        }
#pragma unroll
        for (int j = 0; j < 8; j++) {
            float2 f = upk(dot[j]);
            int code0 = ch * 64 + kg * 16 + 2 * j;
            float d0 = __fadd_rn(__fsub_rn(zz, __fmul_rn(2.0f, f.x)), s_en[code0]);
            float d1 = __fadd_rn(__fsub_rn(zz, __fmul_rn(2.0f, f.y)), s_en[code0 + 1]);
            if (d0 < bv) { bv = d0; bi = code0; }
            if (d1 < bv) { bv = d1; bi = code0 + 1; }
        }
    }
    s_bv[t] = bv;
    s_bi[t] = bi;
    __syncthreads();
    if (t < 64) {
        for (int q = 1; q < 4; q++) {
            float v2 = s_bv[t + q * 64];
            int i2 = s_bi[t + q * 64];
            if (v2 < bv || (v2 == bv && i2 < bi)) { bv = v2; bi = i2; }
        }
        s_idx[t] = bi;
    }
    __syncthreads();
    for (int i = t; i < 4096; i += 256) {
        int c = i >> 6, wq = i & 63;
        zq[(n * 64 + c) * 4096 + h * 64 + wq] = emb[s_idx[wq] * 64 + c];
    }
}

// --------------- d1: convT 64->32, k3 s1 p1, relu; in = ze+(zq-ze) ---------
// Block: 4 oh x 64 ow x 32 oc, 256 thr. Thread: 2 ow (tow+32i) x 16 oc.
__global__ __launch_bounds__(256) void k_d1(const float* __restrict__ ze,
                                            const float* __restrict__ zq,
                                            const float* __restrict__ w,
                                            const float* __restrict__ b) {
    extern __shared__ float sm[];
    float* s_in = sm;            // [r(6)][ic(64)][66] = 25344
    float* s_w  = sm + 25344;    // per (kh,kw): [ic(64)][oc(32)] = 2048
    const int oh0 = blockIdx.x * 4, n = blockIdx.y, t = threadIdx.x;
    const int tow = t & 31, tog = (t >> 5) & 1, toh = t >> 6;   // toh 0..3
    const int lane = t & 31, wrp = t >> 5;
#pragma unroll 1
    for (int m = 0; m < 48; m++) {           // 384 rows = [r6][ic64]
        int row = wrp * 48 + m;
        int r = row >> 6, ic = row & 63;
        int ih = oh0 - 1 + r;
        bool rowok = (ih >= 0 && ih < 64);
        const float* pz = ze + ((n * 64 + ic) * 64 + ih) * 64;
        const float* pq = zq + ((n * 64 + ic) * 64 + ih) * 64;
        float* dst = s_in + row * 66;
#pragma unroll
        for (int k = 0; k < 3; k++) {
            int c = lane + 32 * k;
            if (c < 66) {
                int iw = c - 1;
                float v = 0.f;
                if (rowok && iw >= 0 && iw < 64) {
                    float a = pz[iw], q = pq[iw];
                    v = __fadd_rn(a, __fsub_rn(q, a));
                }
                dst[c] = v;
            }
        }
    }
    u64 acc[2][8];
#pragma unroll
    for (int i = 0; i < 2; i++)
#pragma unroll
        for (int j = 0; j < 8; j++) acc[i][j] = 0ull;
#pragma unroll 1
    for (int kh = 0; kh < 3; kh++) {
#pragma unroll 1
        for (int kw = 0; kw < 3; kw++) {
            __syncthreads();
            for (int i = t; i < 2048; i += 256) {
                int ic = i >> 5, oc = i & 31;
                s_w[i] = w[(ic * 32 + oc) * 9 + 8 - kh * 3 - kw];
            }
            __syncthreads();
            const float* pin = s_in + (toh + kh) * 4224 + tow + kw;
            const float* pwb = s_w + (tog << 4);
#pragma unroll 4
            for (int ic = 0; ic < 64; ic++) {
                const float* pw = pwb + (ic << 5);
                ulonglong2 w0 = *(const ulonglong2*)(pw);
                ulonglong2 w1 = *(const ulonglong2*)(pw + 4);
                ulonglong2 w2 = *(const ulonglong2*)(pw + 8);
                ulonglong2 w3 = *(const ulonglong2*)(pw + 12);
                const float* q = pin + ic * 66;
#pragma unroll
                for (int i = 0; i < 2; i++) {
                    float v = q[32 * i];
                    u64 vv = pk2(v, v);
                    acc[i][0] = f2fma(vv, w0.x, acc[i][0]);
                    acc[i][1] = f2fma(vv, w0.y, acc[i][1]);
                    acc[i][2] = f2fma(vv, w1.x, acc[i][2]);
                    acc[i][3] = f2fma(vv, w1.y, acc[i][3]);
                    acc[i][4] = f2fma(vv, w2.x, acc[i][4]);
                    acc[i][5] = f2fma(vv, w2.y, acc[i][5]);
                    acc[i][6] = f2fma(vv, w3.x, acc[i][6]);
                    acc[i][7] = f2fma(vv, w3.y, acc[i][7]);
                }
            }
        }
    }
    const int oh = oh0 + toh;
#pragma unroll
    for (int i = 0; i < 2; i++) {
        int ow = tow + 32 * i;
#pragma unroll
        for (int j = 0; j < 8; j++) {
            float2 f = upk(acc[i][j]);
            int oc0 = tog * 16 + 2 * j;
            float r0 = f.x + b[oc0];
            float r1 = f.y + b[oc0 + 1];
            g_d1o[((n * 32 + oc0) * 64 + oh) * 64 + ow]     = r0 > 0.f ? r0 : 0.f;
            g_d1o[((n * 32 + oc0 + 1) * 64 + oh) * 64 + ow] = r1 > 0.f ? r1 : 0.f;
        }
    }
}

// --------------- d2 (verbatim R5) ------------------------------------------
__global__ __launch_bounds__(256) void k_d2(const float* __restrict__ w,
                                            const float* __restrict__ b) {
    __shared__ __align__(16) float s_in[2112];   // [r(2)][ic(16)][66]
    __shared__ __align__(16) float s_w[8192];    // [ic(16)][r(2)][kw(4)][oc(64)]
    const int oh = blockIdx.x, n = blockIdx.y, t = threadIdx.x;
    const int p = t & 1, u = (t >> 1) & 15, tog = t >> 5;
    const int lane = t & 31, wrp = t >> 5;
    const int kh_a = 1 - (oh & 1);
    const int ih_a = (oh + 1 - kh_a) >> 1;
    const int kw_a = 1 - p;
    u64 acc[4][4];
#pragma unroll
    for (int i = 0; i < 4; i++)
#pragma unroll
        for (int j = 0; j < 4; j++) acc[i][j] = 0ull;
#pragma unroll 1
    for (int cc = 0; cc < 2; cc++) {
        __syncthreads();
#pragma unroll
        for (int m = 0; m < 4; m++) {
            int row = wrp * 4 + m;
            int r = row >> 4, ic = row & 15;
            int ih = (r == 0) ? ih_a : ih_a - 1;
            bool rowok = (ih >= 0 && ih < 64);
            const float* src = g_d1o + ((n * 32 + cc * 16 + ic) * 64 + ih) * 64;
            float* dst = s_in + row * 66;
#pragma unroll
            for (int k = 0; k < 3; k++) {
                int c = lane + 32 * k;
                if (c < 66) {
                    int iw = c - 1;
                    dst[c] = (rowok && iw >= 0 && iw < 64) ? src[iw] : 0.f;
                }
            }
        }
        for (int i = t; i < 8192; i += 256) {
            int ic = i >> 9, rem = i & 511;
            int r = rem >> 8, kw = (rem >> 6) & 3, oc = rem & 63;
            s_w[i] = w[(((cc * 16 + ic) * 64 + oc) << 4) + (kh_a + 2 * r) * 4 + kw];
        }
        __syncthreads();
#pragma unroll 2
        for (int ic = 0; ic < 16; ic++) {
#pragma unroll
            for (int r = 0; r < 2; r++) {
#pragma unroll
                for (int m = 0; m < 2; m++) {
                    int kw = kw_a + 2 * m;
                    const ulonglong2* pw = (const ulonglong2*)(s_w + ((ic * 2 + r) * 4 + kw) * 64 + tog * 8);
                    const float* q = s_in + r * 1056 + ic * 66 + u + p - m + 1;
                    ulonglong2 w01 = pw[0], w23 = pw[1];
#pragma unroll
                    for (int i = 0; i < 4; i++) {
                        float v = q[16 * i];
                        u64 vv = pk2(v, v);
                        acc[i][0] = f2fma(vv, w01.x, acc[i][0]);
                        acc[i][1] = f2fma(vv, w01.y, acc[i][1]);
                        acc[i][2] = f2fma(vv, w23.x, acc[i][2]);
                        acc[i][3] = f2fma(vv, w23.y, acc[i][3]);
                    }
                }
            }
        }
    }
#pragma unroll
    for (int i = 0; i < 4; i++) {
        int ow = 2 * (u + 16 * i) + p;
#pragma unroll
        for (int j = 0; j < 4; j++) {
            float2 f = upk(acc[i][j]);
            int oc0 = tog * 8 + 2 * j;
            float r0 = f.x + b[oc0];
            float r1 = f.y + b[oc0 + 1];
            g_d2o[((n * 64 + oc0) * 128 + oh) * 128 + ow]     = r0 > 0.f ? r0 : 0.f;
            g_d2o[((n * 64 + oc0 + 1) * 128 + oh) * 128 + ow] = r1 > 0.f ? r1 : 0.f;
        }
    }
}

// --------------- d3 (verbatim R5) ------------------------------------------
__global__ __launch_bounds__(256) void k_d3(const float* __restrict__ w,
                                            const float* __restrict__ bb,
                                            float* __restrict__ xh) {
    __shared__ float s_in[8320];   // [r(2)][ic(32)][130]
    __shared__ float s_w[512];
    const int oh = blockIdx.x, n = blockIdx.y, t = threadIdx.x;
    const int ow = t;
    const int lane = t & 31, wrp = t >> 5;
    const int kh_a = 1 - (oh & 1);
    const int ih_a = (oh + 1 - kh_a) >> 1;
    const int ih_b = ih_a - 1;
    const int kw_a = 1 - (ow & 1);
    const int iw_a = (ow + 1 - kw_a) >> 1;
    for (int i = t; i < 512; i += 256) {
        int ic = i >> 3, r = (i >> 2) & 1, kw = i & 3;
        int kh = kh_a + 2 * r;
        s_w[i] = w[ic * 16 + kh * 4 + kw];
    }
    float acc = 0.f;
#pragma unroll 1
    for (int cc = 0; cc < 2; cc++) {
        __syncthreads();
#pragma unroll
        for (int m = 0; m < 8; m++) {
            int row = wrp * 8 + m;
            int r = row >> 5, ic = row & 31;
            int ih = (r == 0) ? ih_a : ih_b;
            bool rowok = (ih >= 0 && ih < 128);
            const float* src = g_d2o + ((n * 64 + cc * 32 + ic) * 128 + ih) * 128;
            float* dst = s_in + row * 130;
#pragma unroll
            for (int k = 0; k < 5; k++) {
                int c = lane + 32 * k;
                if (c < 130) {
                    int iw = c - 1;
                    dst[c] = (rowok && iw >= 0 && iw < 128) ? src[iw] : 0.f;
                }
            }
        }
        __syncthreads();
#pragma unroll 4
        for (int ic = 0; ic < 32; ic++) {
#pragma unroll
            for (int r = 0; r < 2; r++) {
#pragma unroll
                for (int m = 0; m < 2; m++) {
                    float v = s_in[r * 4160 + ic * 130 + iw_a - m + 1];
                    acc = fmaf(v, s_w[((cc * 32 + ic) << 3) + r * 4 + kw_a + 2 * m], acc);
                }
            }
        }
    }
    xh[n * 65536 + oh * 256 + ow] = __fadd_rn(acc, bb[0]);
}

// ---------------------------------------------------------------------------
extern "C" void kernel_launch(void* const* d_in, const int* in_sizes, int n_in,
                              void* d_out, int out_size) {
    const float* x   = (const float*)d_in[0];
    const float* e1w = (const float*)d_in[1];
    const float* e1b = (const float*)d_in[2];
    const float* e2w = (const float*)d_in[3];
    const float* e2b = (const float*)d_in[4];
    const float* e3w = (const float*)d_in[5];
    const float* e3b = (const float*)d_in[6];
    const float* emb = (const float*)d_in[7];
    const float* d1w = (const float*)d_in[8];
    const float* d1b = (const float*)d_in[9];
    const float* d2w = (const float*)d_in[10];
    const float* d2b = (const float*)d_in[11];
    const float* d3w = (const float*)d_in[12];
    const float* d3b = (const float*)d_in[13];

    float* out = (float*)d_out;
    float* xh = out;
    float* ze = out + 4194304;
    float* zq = out + 4194304 + 16777216;

    static bool attr_done = false;
    if (!attr_done) {
        cudaFuncSetAttribute(k_e2, cudaFuncAttributeMaxDynamicSharedMemorySize, 109568);
        cudaFuncSetAttribute(k_e3, cudaFuncAttributeMaxDynamicSharedMemorySize, 83968);
        cudaFuncSetAttribute(k_d1, cudaFuncAttributeMaxDynamicSharedMemorySize, 109568);
        attr_done = true;
    }

    k_en<<<2, 256>>>(emb);
    k_e1<<<dim3(128, 64), 128>>>(x, e1w, e1b);
    k_e2<<<dim3(32, 64), 256, 109568>>>(e2w, e2b);
    k_e3<<<dim3(32, 64), 256, 83968>>>(e3w, e3b, ze);
    k_vq<<<dim3(64, 64), 256>>>(ze, emb, zq);
    k_d1<<<dim3(16, 64), 256, 109568>>>(ze, zq, d1w, d1b);
    k_d2<<<dim3(128, 64), 256>>>(d2w, d2b);
    k_d3<<<dim3(256, 64), 256>>>(d3w, d3b, xh);
}

// round 10
// speedup vs baseline: 1.0959x; 1.0830x over previous
#include <cuda_runtime.h>

// ---------------------------------------------------------------------------
// VQ-VAE forward, fp32, Eigen-chain-order-exact encoder/VQ, f32x2-packed FMA.
// Round 9: crossbar-budget tiles — e3/vq 8x8 (1 B/FFMA2), e2/d1 4x8 (1.5B);
// warp-uniform weight LDS.128, bank-spread input strides, 2 CTAs/SM.
// ---------------------------------------------------------------------------

typedef unsigned long long u64;

__device__ float g_h1[64 * 32 * 128 * 128];
__device__ float g_h2[64 * 64 * 64 * 64];
__device__ float g_d1o[64 * 32 * 64 * 64];
__device__ float g_d2o[64 * 64 * 128 * 128];
__device__ float g_en[512];
__device__ float g_embT[64 * 512];   // [c][code]

__device__ __forceinline__ u64 pk2(float x, float y) {
    u64 r; asm("mov.b64 %0, {%1, %2};" : "=l"(r) : "f"(x), "f"(y)); return r;
}
__device__ __forceinline__ u64 f2fma(u64 a, u64 b, u64 c) {
    u64 d; asm("fma.rn.f32x2 %0, %1, %2, %3;" : "=l"(d) : "l"(a), "l"(b), "l"(c)); return d;
}
__device__ __forceinline__ float2 upk(u64 v) {
    float2 f; asm("mov.b64 {%0, %1}, %2;" : "=f"(f.x), "=f"(f.y) : "l"(v)); return f;
}

// --------------- codebook norms + transpose --------------------------------
__global__ void k_en(const float* __restrict__ emb) {
    int k = blockIdx.x * blockDim.x + threadIdx.x;
    if (k < 512) {
        float s = 0.f;
        for (int c = 0; c < 64; c++) {
            float v = emb[k * 64 + c];
            s = __fadd_rn(s, __fmul_rn(v, v));
            g_embT[c * 512 + k] = v;
        }
        g_en[k] = s;
    }
}

// ------------------------- e1 (verbatim) -----------------------------------
__global__ __launch_bounds__(128) void k_e1(const float* __restrict__ x,
                                            const float* __restrict__ w,
                                            const float* __restrict__ b) {
    __shared__ float s_in[4 * 258];
    __shared__ float s_w[512];
    const int oh = blockIdx.x, n = blockIdx.y, t = threadIdx.x;
    const int lane = t & 31, wrp = t >> 5;
    {
        int r = wrp;
        int ih = 2 * oh - 1 + r;
        bool rowok = (ih >= 0 && ih < 256);
        const float* src = x + n * 65536 + ih * 256;
        float* dst = s_in + r * 258;
#pragma unroll
        for (int k = 0; k < 9; k++) {
            int c = lane + 32 * k;
            if (c < 258) {
                int iw = c - 1;
                dst[c] = (rowok && iw >= 0 && iw < 256) ? src[iw] : 0.f;
            }
        }
    }
    for (int i = t; i < 512; i += 128) s_w[i] = w[i];
    __syncthreads();
    float acc[32];
#pragma unroll
    for (int o = 0; o < 32; o++) acc[o] = 0.f;
    const int ow = t;
#pragma unroll
    for (int k = 0; k < 16; k++) {
        float v = s_in[(k >> 2) * 258 + 2 * ow + (k & 3)];
#pragma unroll
        for (int o = 0; o < 32; o++) acc[o] = fmaf(v, s_w[o * 16 + k], acc[o]);
    }
    for (int o = 0; o < 32; o++) {
        float r = __fadd_rn(acc[o], b[o]);
        g_h1[((n * 32 + o) * 128 + oh) * 128 + ow] = r > 0.f ? r : 0.f;
    }
}

// ------------------------- e2: 32->64, k4 s2 p1, relu ----------------------
// Block: 32 ow x 64 oc x 4 oh. Thread: tow(8) x toh(4) x tog(8=warp);
// 4 ow (tow+8i) x 8 oc. s_in [ic32][r10][par2][34] (r-stride 68 -> banks
// 8*toh+tow distinct). Chain: kh,kw outer; ic 0..31 innermost (Eigen).
__global__ __launch_bounds__(256) void k_e2(const float* __restrict__ w,
                                            const float* __restrict__ b) {
    extern __shared__ float sm[];
    float* s_in = sm;            // 32*10*68 = 21760
    float* s_w  = sm + 21760;    // per (kh,kw): [ic32][oc64] = 2048
    const int bx = blockIdx.x, n = blockIdx.y, t = threadIdx.x;
    const int ow0 = (bx & 1) * 32, oh0 = (bx >> 1) * 4;
    const int tow = t & 7, toh = (t >> 3) & 3, tog = t >> 5;
    const int lane = t & 31, wrp = t >> 5;
#pragma unroll 1
    for (int m = 0; m < 40; m++) {           // 320 rows = [r10][ic32]
        int row = wrp * 40 + m;
        int r = row >> 5, ic = row & 31;
        int ih = 2 * oh0 - 1 + r;
        bool rowok = (ih >= 0 && ih < 128);
        const float* src = g_h1 + ((n * 32 + ic) * 128 + ih) * 128;
        float* dst = s_in + ic * 680 + r * 68;
#pragma unroll
        for (int k = 0; k < 3; k++) {
            int c = lane + 32 * k;
            if (c < 66) {
                int iw = 2 * ow0 - 1 + c;
                dst[(c & 1) * 34 + (c >> 1)] =
                    (rowok && iw >= 0 && iw < 128) ? src[iw] : 0.f;
            }
        }
    }
    u64 acc[4][4];
#pragma unroll
    for (int i = 0; i < 4; i++)
#pragma unroll
        for (int j = 0; j < 4; j++) acc[i][j] = 0ull;
#pragma unroll 1
    for (int kh = 0; kh < 4; kh++) {
#pragma unroll 1
        for (int kw = 0; kw < 4; kw++) {
            __syncthreads();
            for (int i = t; i < 2048; i += 256) {
                int ic = i >> 6, oc = i & 63;
                s_w[i] = w[((oc * 32 + ic) << 4) + (kh << 2) + kw];
            }
            __syncthreads();
            const float* pin = s_in + (2 * toh + kh) * 68
                                    + (kw & 1) * 34 + (kw >> 1) + tow;
            const float* pwb = s_w + (tog << 3);
#pragma unroll 4
            for (int ic = 0; ic < 32; ic++) {
                const float* pw = pwb + (ic << 6);
                ulonglong2 wa = *(const ulonglong2*)(pw);
                ulonglong2 wb = *(const ulonglong2*)(pw + 4);
                const float* q = pin + ic * 680;
#pragma unroll
                for (int i = 0; i < 4; i++) {
                    float v = q[8 * i];
                    u64 vv = pk2(v, v);
                    acc[i][0] = f2fma(vv, wa.x, acc[i][0]);
                    acc[i][1] = f2fma(vv, wa.y, acc[i][1]);
                    acc[i][2] = f2fma(vv, wb.x, acc[i][2]);
                    acc[i][3] = f2fma(vv, wb.y, acc[i][3]);
                }
            }
        }
    }
    const int oh = oh0 + toh;
#pragma unroll
    for (int i = 0; i < 4; i++) {
        int ow = ow0 + tow + 8 * i;
#pragma unroll
        for (int j = 0; j < 4; j++) {
            float2 f = upk(acc[i][j]);
            int oc0 = tog * 8 + 2 * j;
            float r0 = __fadd_rn(f.x, b[oc0]);
            float r1 = __fadd_rn(f.y, b[oc0 + 1]);
            g_h2[((n * 64 + oc0) * 64 + oh) * 64 + ow]     = r0 > 0.f ? r0 : 0.f;
            g_h2[((n * 64 + oc0 + 1) * 64 + oh) * 64 + ow] = r1 > 0.f ? r1 : 0.f;
        }
    }
}

// ------------------------- e3: 64->64, k3 s1 p1, relu ----------------------
// Block: 32 ow x 64 oc x 8 oh. Thread: tow(4) x toh(8) x tog(8=warp);
// 8 ow (tow+4i) x 8 oc. s_in [ic64][r10][36] (banks 4*toh+tow distinct).
__global__ __launch_bounds__(256) void k_e3(const float* __restrict__ w,
                                            const float* __restrict__ b,
                                            float* __restrict__ ze) {
    extern __shared__ float sm[];
    float* s_in = sm;            // 64*360 = 23040
    float* s_w  = sm + 23040;    // per (kh,kw): [ic64][oc64] = 4096
    const int bx = blockIdx.x, n = blockIdx.y, t = threadIdx.x;
    const int ow0 = (bx & 1) * 32, oh0 = (bx >> 1) * 8;
    const int tow = t & 3, toh = (t >> 2) & 7, tog = t >> 5;
    const int lane = t & 31, wrp = t >> 5;
#pragma unroll 1
    for (int m = 0; m < 80; m++) {           // 640 rows = [r10][ic64]
        int row = wrp * 80 + m;
        int r = row >> 6, ic = row & 63;
        int ih = oh0 - 1 + r;
        bool rowok = (ih >= 0 && ih < 64);
        const float* src = g_h2 + ((n * 64 + ic) * 64 + ih) * 64;
        float* dst = s_in + ic * 360 + r * 36;
        {
            int c = lane;
            int iw = ow0 + c - 1;
            dst[c] = (rowok && iw >= 0 && iw < 64) ? src[iw] : 0.f;
        }
        if (lane < 2) {
            int c = 32 + lane;
            int iw = ow0 + c - 1;
            dst[c] = (rowok && iw >= 0 && iw < 64) ? src[iw] : 0.f;
        }
    }
    u64 acc[8][4];
#pragma unroll
    for (int i = 0; i < 8; i++)
#pragma unroll
        for (int j = 0; j < 4; j++) acc[i][j] = 0ull;
#pragma unroll 1
    for (int kh = 0; kh < 3; kh++) {
#pragma unroll 1
        for (int kw = 0; kw < 3; kw++) {
            __syncthreads();
            for (int i = t; i < 4096; i += 256) {
                int ic = i >> 6, oc = i & 63;
                s_w[i] = w[(oc * 64 + ic) * 9 + kh * 3 + kw];
            }
            __syncthreads();
            const float* pin = s_in + (toh + kh) * 36 + tow + kw;
            const float* pwb = s_w + (tog << 3);
#pragma unroll 2
            for (int ic = 0; ic < 64; ic++) {
                const float* pw = pwb + (ic << 6);
                ulonglong2 wa = *(const ulonglong2*)(pw);
                ulonglong2 wb = *(const ulonglong2*)(pw + 4);
                const float* q = pin + ic * 360;
#pragma unroll
                for (int i = 0; i < 8; i++) {
                    float v = q[4 * i];
                    u64 vv = pk2(v, v);
                    acc[i][0] = f2fma(vv, wa.x, acc[i][0]);
                    acc[i][1] = f2fma(vv, wa.y, acc[i][1]);
                    acc[i][2] = f2fma(vv, wb.x, acc[i][2]);
                    acc[i][3] = f2fma(vv, wb.y, acc[i][3]);
                }
            }
        }
    }
    const int oh = oh0 + toh;
#pragma unroll
    for (int i = 0; i < 8; i++) {
        int ow = ow0 + tow + 4 * i;
#pragma unroll
        for (int j = 0; j < 4; j++) {
            float2 f = upk(acc[i][j]);
            int oc0 = tog * 8 + 2 * j;
            float r0 = __fadd_rn(f.x, b[oc0]);
            float r1 = __fadd_rn(f.y, b[oc0 + 1]);
            ze[((n * 64 + oc0) * 64 + oh) * 64 + ow]     = r0 > 0.f ? r0 : 0.f;
            ze[((n * 64 + oc0 + 1) * 64 + oh) * 64 + ow] = r1 > 0.f ? r1 : 0.f;
        }
    }
}

// ------------------------- VQ argmin + gather ------------------------------
// Block: 4 h rows x 64 pos. Thread: tpos(8) x th(4) x kg(8=warp);
// 8 pos (tpos+8i) x 8 codes per ch. s_z plane stride 4104 (banks 8*th+tpos).
__global__ __launch_bounds__(256) void k_vq(const float* __restrict__ ze,
                                            const float* __restrict__ emb,
                                            float* __restrict__ zq) {
    extern __shared__ float sm[];
    float* s_z  = sm;            // [hh4 stride 4104] = 16416
    float* s_e  = sm + 16416;    // [c64][code64] = 4096
    float* s_en = sm + 20512;    // 512
    float* s_zz = sm + 21024;    // [hh4 stride 72] = 288
    float* s_bv = sm + 21312;    // [kg8][th4][pos64] = 2048
    int*   s_bi = (int*)(sm + 23360);   // 2048
    int*   s_idx = (int*)(sm + 25408);  // [hh4][pos64] = 256
    const int h0 = blockIdx.x * 4, n = blockIdx.y, t = threadIdx.x;
    const int tpos = t & 7, th = (t >> 3) & 3, kg = t >> 5;
    for (int i = t; i < 16384; i += 256) {
        int c = i >> 8, hh = (i >> 6) & 3, pos = i & 63;
        s_z[hh * 4104 + c * 64 + pos] =
            ze[n * 262144 + c * 4096 + (h0 + hh) * 64 + pos];
    }
    for (int i = t; i < 512; i += 256) s_en[i] = g_en[i];
    __syncthreads();
    {
        int hh = t >> 6, pp = t & 63;
        float a = 0.f;
        for (int c = 0; c < 64; c++) {
            float v = s_z[hh * 4104 + c * 64 + pp];
            a = __fadd_rn(a, __fmul_rn(v, v));
        }
        s_zz[hh * 72 + pp] = a;
    }
    float bv[8];
    int bi[8];
#pragma unroll
    for (int i = 0; i < 8; i++) { bv[i] = 3.4e38f; bi[i] = 0; }
#pragma unroll 1
    for (int ch = 0; ch < 8; ch++) {
        __syncthreads();
        for (int i = t; i < 4096; i += 256)
            s_e[i] = g_embT[(i >> 6) * 512 + ch * 64 + (i & 63)];
        __syncthreads();
        u64 dot[8][4];
#pragma unroll
        for (int i = 0; i < 8; i++)
#pragma unroll
            for (int j = 0; j < 4; j++) dot[i][j] = 0ull;
        const float* pz = s_z + th * 4104 + tpos;
        const float* peb = s_e + kg * 8;
#pragma unroll 2
        for (int c = 0; c < 64; c++) {
            const float* pe = peb + (c << 6);
            ulonglong2 e01 = *(const ulonglong2*)(pe);
            ulonglong2 e23 = *(const ulonglong2*)(pe + 4);
            const float* q = pz + (c << 6);
#pragma unroll
            for (int i = 0; i < 8; i++) {
                float v = q[8 * i];
                u64 vv = pk2(v, v);
                dot[i][0] = f2fma(vv, e01.x, dot[i][0]);
                dot[i][1] = f2fma(vv, e01.y, dot[i][1]);
                dot[i][2] = f2fma(vv, e23.x, dot[i][2]);
                dot[i][3] = f2fma(vv, e23.y, dot[i][3]);
            }
        }
#pragma unroll
        for (int i = 0; i < 8; i++) {
            float zz = s_zz[th * 72 + tpos + 8 * i];
#pragma unroll
            for (int j = 0; j < 4; j++) {
                float2 f = upk(dot[i][j]);
                int code0 = ch * 64 + kg * 8 + 2 * j;
                float d0 = __fadd_rn(__fsub_rn(zz, __fmul_rn(2.0f, f.x)), s_en[code0]);
                float d1 = __fadd_rn(__fsub_rn(zz, __fmul_rn(2.0f, f.y)), s_en[code0 + 1]);
                if (d0 < bv[i]) { bv[i] = d0; bi[i] = code0; }
                if (d1 < bv[i]) { bv[i] = d1; bi[i] = code0 + 1; }
            }
        }
    }
#pragma unroll
    for (int i = 0; i < 8; i++) {
        int pos = tpos + 8 * i;
        s_bv[(kg * 4 + th) * 64 + pos] = bv[i];
        s_bi[(kg * 4 + th) * 64 + pos] = bi[i];
    }
    __syncthreads();
    {
        int hh = t >> 6, pp = t & 63;
        float bb = s_bv[hh * 64 + pp];
        int ii = s_bi[hh * 64 + pp];
        for (int q = 1; q < 8; q++) {
            float v2 = s_bv[(q * 4 + hh) * 64 + pp];
            int i2 = s_bi[(q * 4 + hh) * 64 + pp];
            if (v2 < bb || (v2 == bb && i2 < ii)) { bb = v2; ii = i2; }
        }
        s_idx[hh * 64 + pp] = ii;
    }
    __syncthreads();
    for (int i = t; i < 16384; i += 256) {
        int c = i >> 8, hh = (i >> 6) & 3, wq = i & 63;
        zq[n * 262144 + c * 4096 + (h0 + hh) * 64 + wq] =
            emb[s_idx[hh * 64 + wq] * 64 + c];
    }
}

// --------------- d1: convT 64->32, k3 s1 p1, relu; in = ze+(zq-ze) ---------
// Block: 32 ow x 32 oc x 8 oh. Thread: tow(8) x toh(8) x tog(4);
// 4 ow (tow+8i) x 8 oc. s_in [ic64][r10][40] (banks 8*toh'+tow distinct).
__global__ __launch_bounds__(256) void k_d1(const float* __restrict__ ze,
                                            const float* __restrict__ zq,
                                            const float* __restrict__ w,
                                            const float* __restrict__ b) {
    extern __shared__ float sm[];
    float* s_in = sm;            // 64*400 = 25600
    float* s_w  = sm + 25600;    // per (kh,kw): [ic64][oc32] = 2048
    const int bx = blockIdx.x, n = blockIdx.y, t = threadIdx.x;
    const int ow0 = (bx & 1) * 32, oh0 = (bx >> 1) * 8;
    const int tow = t & 7, toh = (t >> 3) & 7, tog = t >> 6;
    const int lane = t & 31, wrp = t >> 5;
#pragma unroll 1
    for (int m = 0; m < 80; m++) {           // 640 rows = [r10][ic64]
        int row = wrp * 80 + m;
        int r = row >> 6, ic = row & 63;
        int ih = oh0 - 1 + r;
        bool rowok = (ih >= 0 && ih < 64);
        const float* pz = ze + ((n * 64 + ic) * 64 + ih) * 64;
        const float* pq = zq + ((n * 64 + ic) * 64 + ih) * 64;
        float* dst = s_in + ic * 400 + r * 40;
        {
            int c = lane;
            int iw = ow0 + c - 1;
            float v = 0.f;
            if (rowok && iw >= 0 && iw < 64) {
                float a = pz[iw], q = pq[iw];
                v = __fadd_rn(a, __fsub_rn(q, a));
            }
            dst[c] = v;
        }
        if (lane < 2) {
            int c = 32 + lane;
            int iw = ow0 + c - 1;
            float v = 0.f;
            if (rowok && iw >= 0 && iw < 64) {
                float a = pz[iw], q = pq[iw];
                v = __fadd_rn(a, __fsub_rn(q, a));
            }
            dst[c] = v;
        }
    }
    u64 acc[4][4];
#pragma unroll
    for (int i = 0; i < 4; i++)
#pragma unroll
        for (int j = 0; j < 4; j++) acc[i][j] = 0ull;
#pragma unroll 1
    for (int kh = 0; kh < 3; kh++) {
#pragma unroll 1
        for (int kw = 0; kw < 3; kw++) {
            __syncthreads();
            for (int i = t; i < 2048; i += 256) {
                int ic = i >> 5, oc = i & 31;
                s_w[i] = w[(ic * 32 + oc) * 9 + 8 - kh * 3 - kw];
            }
            __syncthreads();
            const float* pin = s_in + (toh + kh) * 40 + tow + kw;
            const float* pwb = s_w + (tog << 3);
#pragma unroll 2
            for (int ic = 0; ic < 64; ic++) {
                const float* pw = pwb + (ic << 5);
                ulonglong2 wa = *(const ulonglong2*)(pw);
                ulonglong2 wb = *(const ulonglong2*)(pw + 4);
                const float* q = pin + ic * 400;
#pragma unroll
                for (int i = 0; i < 4; i++) {
                    float v = q[8 * i];
                    u64 vv = pk2(v, v);
                    acc[i][0] = f2fma(vv, wa.x, acc[i][0]);
                    acc[i][1] = f2fma(vv, wa.y, acc[i][1]);
                    acc[i][2] = f2fma(vv, wb.x, acc[i][2]);
                    acc[i][3] = f2fma(vv, wb.y, acc[i][3]);
                }
            }
        }
    }
    const int oh = oh0 + toh;
#pragma unroll
    for (int i = 0; i < 4; i++) {
        int ow = ow0 + tow + 8 * i;
#pragma unroll
        for (int j = 0; j < 4; j++) {
            float2 f = upk(acc[i][j]);
            int oc0 = tog * 8 + 2 * j;
            float r0 = f.x + b[oc0];
            float r1 = f.y + b[oc0 + 1];
            g_d1o[((n * 32 + oc0) * 64 + oh) * 64 + ow]     = r0 > 0.f ? r0 : 0.f;
            g_d1o[((n * 32 + oc0 + 1) * 64 + oh) * 64 + ow] = r1 > 0.f ? r1 : 0.f;
        }
    }
}

// --------------- d2 (verbatim R5) ------------------------------------------
__global__ __launch_bounds__(256) void k_d2(const float* __restrict__ w,
                                            const float* __restrict__ b) {
    __shared__ __align__(16) float s_in[2112];
    __shared__ __align__(16) float s_w[8192];
    const int oh = blockIdx.x, n = blockIdx.y, t = threadIdx.x;
    const int p = t & 1, u = (t >> 1) & 15, tog = t >> 5;
    const int lane = t & 31, wrp = t >> 5;
    const int kh_a = 1 - (oh & 1);
    const int ih_a = (oh + 1 - kh_a) >> 1;
    const int kw_a = 1 - p;
    u64 acc[4][4];
#pragma unroll
    for (int i = 0; i < 4; i++)
#pragma unroll
        for (int j = 0; j < 4; j++) acc[i][j] = 0ull;
#pragma unroll 1
    for (int cc = 0; cc < 2; cc++) {
        __syncthreads();
#pragma unroll
        for (int m = 0; m < 4; m++) {
            int row = wrp * 4 + m;
            int r = row >> 4, ic = row & 15;
            int ih = (r == 0) ? ih_a : ih_a - 1;
            bool rowok = (ih >= 0 && ih < 64);
            const float* src = g_d1o + ((n * 32 + cc * 16 + ic) * 64 + ih) * 64;
            float* dst = s_in + row * 66;
#pragma unroll
            for (int k = 0; k < 3; k++) {
                int c = lane + 32 * k;
                if (c < 66) {
                    int iw = c - 1;
                    dst[c] = (rowok && iw >= 0 && iw < 64) ? src[iw] : 0.f;
                }
            }
        }
        for (int i = t; i < 8192; i += 256) {
            int ic = i >> 9, rem = i & 511;
            int r = rem >> 8, kw = (rem >> 6) & 3, oc = rem & 63;
            s_w[i] = w[(((cc * 16 + ic) * 64 + oc) << 4) + (kh_a + 2 * r) * 4 + kw];
        }
        __syncthreads();
#pragma unroll 2
        for (int ic = 0; ic < 16; ic++) {
#pragma unroll
            for (int r = 0; r < 2; r++) {
#pragma unroll
                for (int m = 0; m < 2; m++) {
                    int kw = kw_a + 2 * m;
                    const ulonglong2* pw = (const ulonglong2*)(s_w + ((ic * 2 + r) * 4 + kw) * 64 + tog * 8);
                    const float* q = s_in + r * 1056 + ic * 66 + u + p - m + 1;
                    ulonglong2 w01 = pw[0], w23 = pw[1];
#pragma unroll
                    for (int i = 0; i < 4; i++) {
                        float v = q[16 * i];
                        u64 vv = pk2(v, v);
                        acc[i][0] = f2fma(vv, w01.x, acc[i][0]);
                        acc[i][1] = f2fma(vv, w01.y, acc[i][1]);
                        acc[i][2] = f2fma(vv, w23.x, acc[i][2]);
                        acc[i][3] = f2fma(vv, w23.y, acc[i][3]);
                    }
                }
            }
        }
    }
#pragma unroll
    for (int i = 0; i < 4; i++) {
        int ow = 2 * (u + 16 * i) + p;
#pragma unroll
        for (int j = 0; j < 4; j++) {
            float2 f = upk(acc[i][j]);
            int oc0 = tog * 8 + 2 * j;
            float r0 = f.x + b[oc0];
            float r1 = f.y + b[oc0 + 1];
            g_d2o[((n * 64 + oc0) * 128 + oh) * 128 + ow]     = r0 > 0.f ? r0 : 0.f;
            g_d2o[((n * 64 + oc0 + 1) * 128 + oh) * 128 + ow] = r1 > 0.f ? r1 : 0.f;
        }
    }
}

// --------------- d3 (verbatim R5) ------------------------------------------
__global__ __launch_bounds__(256) void k_d3(const float* __restrict__ w,
                                            const float* __restrict__ bb,
                                            float* __restrict__ xh) {
    __shared__ float s_in[8320];
    __shared__ float s_w[512];
    const int oh = blockIdx.x, n = blockIdx.y, t = threadIdx.x;
    const int ow = t;
    const int lane = t & 31, wrp = t >> 5;
    const int kh_a = 1 - (oh & 1);
    const int ih_a = (oh + 1 - kh_a) >> 1;
    const int ih_b = ih_a - 1;
    const int kw_a = 1 - (ow & 1);
    const int iw_a = (ow + 1 - kw_a) >> 1;
    for (int i = t; i < 512; i += 256) {
        int ic = i >> 3, r = (i >> 2) & 1, kw = i & 3;
        int kh = kh_a + 2 * r;
        s_w[i] = w[ic * 16 + kh * 4 + kw];
    }
    float acc = 0.f;
#pragma unroll 1
    for (int cc = 0; cc < 2; cc++) {
        __syncthreads();
#pragma unroll
        for (int m = 0; m < 8; m++) {
            int row = wrp * 8 + m;
            int r = row >> 5, ic = row & 31;
            int ih = (r == 0) ? ih_a : ih_b;
            bool rowok = (ih >= 0 && ih < 128);
            const float* src = g_d2o + ((n * 64 + cc * 32 + ic) * 128 + ih) * 128;
            float* dst = s_in + row * 130;
#pragma unroll
            for (int k = 0; k < 5; k++) {
                int c = lane + 32 * k;
                if (c < 130) {
                    int iw = c - 1;
                    dst[c] = (rowok && iw >= 0 && iw < 128) ? src[iw] : 0.f;
                }
            }
        }
        __syncthreads();
#pragma unroll 4
        for (int ic = 0; ic < 32; ic++) {
#pragma unroll
            for (int r = 0; r < 2; r++) {
#pragma unroll
                for (int m = 0; m < 2; m++) {
                    float v = s_in[r * 4160 + ic * 130 + iw_a - m + 1];
                    acc = fmaf(v, s_w[((cc * 32 + ic) << 3) + r * 4 + kw_a + 2 * m], acc);
                }
            }
        }
    }
    xh[n * 65536 + oh * 256 + ow] = __fadd_rn(acc, bb[0]);
}

// ---------------------------------------------------------------------------
extern "C" void kernel_launch(void* const* d_in, const int* in_sizes, int n_in,
                              void* d_out, int out_size) {
    const float* x   = (const float*)d_in[0];
    const float* e1w = (const float*)d_in[1];
    const float* e1b = (const float*)d_in[2];
    const float* e2w = (const float*)d_in[3];
    const float* e2b = (const float*)d_in[4];
    const float* e3w = (const float*)d_in[5];
    const float* e3b = (const float*)d_in[6];
    const float* emb = (const float*)d_in[7];
    const float* d1w = (const float*)d_in[8];
    const float* d1b = (const float*)d_in[9];
    const float* d2w = (const float*)d_in[10];
    const float* d2b = (const float*)d_in[11];
    const float* d3w = (const float*)d_in[12];
    const float* d3b = (const float*)d_in[13];

    float* out = (float*)d_out;
    float* xh = out;
    float* ze = out + 4194304;
    float* zq = out + 4194304 + 16777216;

    static bool attr_done = false;
    if (!attr_done) {
        cudaFuncSetAttribute(k_e2, cudaFuncAttributeMaxDynamicSharedMemorySize, 95232);
        cudaFuncSetAttribute(k_e3, cudaFuncAttributeMaxDynamicSharedMemorySize, 108544);
        cudaFuncSetAttribute(k_d1, cudaFuncAttributeMaxDynamicSharedMemorySize, 110592);
        cudaFuncSetAttribute(k_vq, cudaFuncAttributeMaxDynamicSharedMemorySize, 102656);
        attr_done = true;
    }

    k_en<<<2, 256>>>(emb);
    k_e1<<<dim3(128, 64), 128>>>(x, e1w, e1b);
    k_e2<<<dim3(32, 64), 256, 95232>>>(e2w, e2b);
    k_e3<<<dim3(16, 64), 256, 108544>>>(e3w, e3b, ze);
    k_vq<<<dim3(16, 64), 256, 102656>>>(ze, emb, zq);
    k_d1<<<dim3(16, 64), 256, 110592>>>(ze, zq, d1w, d1b);
    k_d2<<<dim3(128, 64), 256>>>(d2w, d2b);
    k_d3<<<dim3(256, 64), 256>>>(d3w, d3b, xh);
}